// round 1
// baseline (speedup 1.0000x reference)
#include <cuda_runtime.h>
#include <cuda_bf16.h>

// Problem constants (from reference): B=16, C=128, H=W=224, KS=3, STRIDE=2,
// ALPHA=16 -> h[z] = -(z/t)^16 for z in {0,1,2}; Ho=Wo=111.
#define B_  16
#define C_  128
#define H_  224
#define W_  224
#define HO_ 111
#define WO_ 111
#define ROWS_PER_BLOCK 4

__global__ __launch_bounds__(128)
void lfp_kernel(const float* __restrict__ f,
                const float* __restrict__ t,
                float* __restrict__ out)
{
    const int j = threadIdx.x;                 // output column 0..WO_-1
    if (j >= WO_) return;
    const int bc = blockIdx.z;                 // b*C + c
    const int c  = bc & (C_ - 1);

    // Per-channel additive kernel values: h0 = 0, h1 = -(1/t)^16, h2 = -(2/t)^16
    const float inv = 1.0f / __ldg(t + c);
    const float x2  = inv * inv;
    const float x4  = x2 * x2;
    const float x8  = x4 * x4;
    const float x16 = x8 * x8;
    const float h1  = -x16;
    const float h2  = -65536.0f * x16;         // 2^16 * inv^16

    const float* __restrict__ fb = f + (size_t)bc * (H_ * W_) + 2 * j;
    float* __restrict__ ob = out + (size_t)bc * (HO_ * WO_);

    const int i0   = blockIdx.y * ROWS_PER_BLOCK;
    int       iend = i0 + ROWS_PER_BLOCK;
    if (iend > HO_) iend = HO_;

    // Per input row r: center c_j = f[r,2j+1], edge e_j = max(f[r,2j], f[r,2j+2])
    const float* p = fb + (size_t)(2 * i0) * W_;
    float a  = p[0], b = p[1], d = p[2];
    float c0 = b, e0 = fmaxf(a, d);

    for (int i = i0; i < iend; ++i) {
        const float* p1 = fb + (size_t)(2 * i + 1) * W_;
        const float* p2 = fb + (size_t)(2 * i + 2) * W_;
        float a1 = p1[0], b1 = p1[1], d1 = p1[2];
        float a2 = p2[0], b2 = p2[1], d2 = p2[2];
        float c1 = b1, e1 = fmaxf(a1, d1);
        float c2 = b2, e2 = fmaxf(a2, d2);

        // out = max(center_mid, edges_mid + h1, centers_top/bot + h1, edges_top/bot + h2)
        float v = c1;
        v = fmaxf(v, e1 + h1);
        v = fmaxf(v, fmaxf(c0, c2) + h1);
        v = fmaxf(v, fmaxf(e0, e2) + h2);
        ob[(size_t)i * WO_ + j] = v;

        c0 = c2; e0 = e2;
    }
}

extern "C" void kernel_launch(void* const* d_in, const int* in_sizes, int n_in,
                              void* d_out, int out_size)
{
    const float* f = (const float*)d_in[0];
    const float* t = (const float*)d_in[1];
    float* out = (float*)d_out;

    dim3 block(128, 1, 1);
    dim3 grid(1, (HO_ + ROWS_PER_BLOCK - 1) / ROWS_PER_BLOCK, B_ * C_);
    lfp_kernel<<<grid, block>>>(f, t, out);
}